// round 11
// baseline (speedup 1.0000x reference)
#include <cuda_runtime.h>
#include <cstdint>

// HELoss: loss = mean_i [ logsumexp_j(s*logits[i,j] with label col -> s*(l_y - cm)) - s*(l_y - cm) ]
// N=8192 rows, C=32000 cols, s=30. HBM-bound streaming row-LSE.
// R11: 256-bit streaming loads (ld.global.nc.L2::evict_first.v8.b32 — the only
// legal evict_first form on sm_103a per ptxas). Halves load-instruction count
// and applies evict-first L2 policy to the read-once stream.
// Reduction: fire-and-forget fixed-point RED.ADD.64 (order-independent ->
// bitwise deterministic), finalized by a <<<1,1>>> PDL secondary.

constexpr int N_ROWS = 8192;
constexpr int N_COLS = 32000;
constexpr int NCHUNK = N_COLS / 8;      // 4000 v8-chunks (32B) per row
constexpr float S_SCALE = 30.0f;
constexpr float K_L2E   = 30.0f * 1.44269504088896340736f; // S * log2(e)
constexpr float LN2F    = 0.693147180559945309f;
constexpr float NEG_BIG = -3.402823466e38f;
constexpr double FIXED_SCALE = 4294967296.0;   // 2^32

__device__ unsigned long long g_acc = 0ull;    // fixed-point loss accumulator

struct f8 { float v[8]; };

static __device__ __forceinline__ float ex2f_(float x) {
    float y; asm("ex2.approx.ftz.f32 %0, %1;" : "=f"(y) : "f"(x)); return y;
}
static __device__ __forceinline__ float lg2f_(float x) {
    float y; asm("lg2.approx.ftz.f32 %0, %1;" : "=f"(y) : "f"(x)); return y;
}

// Fire-and-forget relaxed reduction: RED.ADD.64, no return, no wait.
static __device__ __forceinline__ void red_add_u64(unsigned long long* p,
                                                   unsigned long long v) {
    asm volatile("red.relaxed.gpu.global.add.u64 [%0], %1;"
                 :: "l"(p), "l"(v) : "memory");
}

// 256-bit streaming load: non-coherent + L2 evict-first (read-once data).
static __device__ __forceinline__ f8 ldg_stream_v8(const float* p) {
    unsigned int r0, r1, r2, r3, r4, r5, r6, r7;
    asm("ld.global.nc.L2::evict_first.v8.b32 {%0,%1,%2,%3,%4,%5,%6,%7}, [%8];"
        : "=r"(r0), "=r"(r1), "=r"(r2), "=r"(r3),
          "=r"(r4), "=r"(r5), "=r"(r6), "=r"(r7)
        : "l"(p));
    f8 o;
    o.v[0] = __uint_as_float(r0); o.v[1] = __uint_as_float(r1);
    o.v[2] = __uint_as_float(r2); o.v[3] = __uint_as_float(r3);
    o.v[4] = __uint_as_float(r4); o.v[5] = __uint_as_float(r5);
    o.v[6] = __uint_as_float(r6); o.v[7] = __uint_as_float(r7);
    return o;
}

// Load the 2 v8-chunks (16 floats) for iteration `it`.
// Chunks 0..14 (x256) are compile-time in range; only the final chunk is guarded.
static __device__ __forceinline__ void load_iter(const float* __restrict__ rowp,
                                                 int tid, int it, f8 v[2]) {
    #pragma unroll
    for (int j = 0; j < 2; ++j) {
        const int cidx = tid + (it * 2 + j) * 256;
        if ((it * 2 + j + 1) * 256 <= NCHUNK) {
            v[j] = ldg_stream_v8(rowp + cidx * 8);           // compile-time safe
        } else {
            if (cidx < NCHUNK) v[j] = ldg_stream_v8(rowp + cidx * 8);
            else {
                #pragma unroll
                for (int k = 0; k < 8; ++k) v[j].v[k] = NEG_BIG;
            }
        }
    }
}

static __device__ __forceinline__ void consume_iter(const f8 v[2],
                                                    float& m, float& s) {
    // chunk max over 16 values (tree)
    float a0 = fmaxf(fmaxf(v[0].v[0], v[0].v[1]), fmaxf(v[0].v[2], v[0].v[3]));
    float a1 = fmaxf(fmaxf(v[0].v[4], v[0].v[5]), fmaxf(v[0].v[6], v[0].v[7]));
    float a2 = fmaxf(fmaxf(v[1].v[0], v[1].v[1]), fmaxf(v[1].v[2], v[1].v[3]));
    float a3 = fmaxf(fmaxf(v[1].v[4], v[1].v[5]), fmaxf(v[1].v[6], v[1].v[7]));
    float cmx = fmaxf(fmaxf(a0, a1), fmaxf(a2, a3));
    float nm = fmaxf(m, cmx);
    float scale = ex2f_((m - nm) * K_L2E);  // ==1 when max unchanged
    m = nm;
    const float nmK = -m * K_L2E;
    float e[16];
    #pragma unroll
    for (int k = 0; k < 8; ++k) e[k]     = ex2f_(fmaf(v[0].v[k], K_L2E, nmK));
    #pragma unroll
    for (int k = 0; k < 8; ++k) e[8 + k] = ex2f_(fmaf(v[1].v[k], K_L2E, nmK));
    float t0 = (e[0]  + e[1])  + (e[2]  + e[3]);
    float t1 = (e[4]  + e[5])  + (e[6]  + e[7]);
    float t2 = (e[8]  + e[9])  + (e[10] + e[11]);
    float t3 = (e[12] + e[13]) + (e[14] + e[15]);
    float csum = (t0 + t1) + (t2 + t3);
    s = fmaf(s, scale, csum);
}

__global__ void __launch_bounds__(256)
row_lse_kernel(const float* __restrict__ logits,
               const unsigned int* __restrict__ labels_raw,
               const float* __restrict__ cm_ptr) {
    const int row = blockIdx.x;
    const int tid = threadIdx.x;

    const float* rowp = logits + (size_t)row * N_COLS;

    float m = NEG_BIG;
    float s = 0.0f;

    // Software pipeline: prefetch depth 1. Per-warp in flight: 4 LDG.256 = 128B/thread-pair
    // (same bytes as R9's 8 LDG.128, half the instructions).
    f8 cur[2], nxt[2];
    load_iter(rowp, tid, 0, cur);
    #pragma unroll
    for (int it = 0; it < 8; ++it) {
        if (it < 7) load_iter(rowp, tid, it + 1, nxt);
        consume_iter(cur, m, s);
        if (it < 7) { cur[0] = nxt[0]; cur[1] = nxt[1]; }
    }

    // warp combine (m, s)
    #pragma unroll
    for (int o = 16; o > 0; o >>= 1) {
        float mo = __shfl_down_sync(0xffffffffu, m, o);
        float so = __shfl_down_sync(0xffffffffu, s, o);
        float M  = fmaxf(m, mo);
        s = s * ex2f_((m - M) * K_L2E) + so * ex2f_((mo - M) * K_L2E);
        m = M;
    }

    __shared__ float sm_m[8];
    __shared__ float sm_s[8];
    const int wid = tid >> 5;
    if ((tid & 31) == 0) { sm_m[wid] = m; sm_s[wid] = s; }
    __syncthreads();

    if (tid < 32) {
        float m2 = (tid < 8) ? sm_m[tid] : NEG_BIG;
        float s2 = (tid < 8) ? sm_s[tid] : 0.0f;
        #pragma unroll
        for (int o = 4; o > 0; o >>= 1) {
            float mo = __shfl_down_sync(0xffffffffu, m2, o);
            float so = __shfl_down_sync(0xffffffffu, s2, o);
            float M  = fmaxf(m2, mo);
            s2 = s2 * ex2f_((m2 - M) * K_L2E) + so * ex2f_((mo - M) * K_L2E);
            m2 = M;
        }

        // In-warp label-width detection: int64 little-endian labels (< 32000)
        // have all-zero odd 32-bit words. False-positive prob for int32 random
        // labels ~ (1/32000)^32 ~= 0. L2-broadcast reads.
        unsigned int oddw = labels_raw[2 * tid + 1];
        unsigned int mask = __ballot_sync(0xffffffffu, oddw == 0u);
        if (tid == 0) {
            const bool is64 = (mask == 0xffffffffu);
            int lab;
            if (is64) lab = (int)((const long long*)labels_raw)[row];
            else      lab = ((const int*)labels_raw)[row];

            const float cm = __ldg(cm_ptr);
            const float a  = __ldg(rowp + lab);   // raw label logit
            const float ap = a - cm;              // substituted value
            // Post-hoc LSE correction: swap exp(K*a) term for exp(K*ap).
            // Bitwise no-op when cm == 0.
            const float M  = fmaxf(m2, ap);
            const float sc = ex2f_((m2 - M) * K_L2E);
            float sp = fmaf(s2, sc, ex2f_((ap - M) * K_L2E) - ex2f_((a - M) * K_L2E));
            const float lse = S_SCALE * M + lg2f_(sp) * LN2F;  // natural-log LSE
            const float loss = lse - S_SCALE * ap;             // >= 0 always

            // Deterministic accumulation: fixed-point (2^-32) integer RED —
            // associative, order-independent, no ordering semantics -> no
            // write-drain stall, no return wait.
            long long q = __double2ll_rn((double)loss * FIXED_SCALE);
            red_add_u64(&g_acc, (unsigned long long)q);
        }
    }
}

__global__ void finalize_kernel(float* __restrict__ out) {
    // PDL: launch overlaps the primary's tail; grid-dependency sync plus the
    // primary's kernel-completion flush make all REDs visible here.
    cudaGridDependencySynchronize();
    double v = (double)(long long)g_acc;
    out[0] = (float)(v * (1.0 / FIXED_SCALE) * (1.0 / (double)N_ROWS));
    g_acc = 0ull;   // reset for the next graph replay (stream-ordered)
}

extern "C" void kernel_launch(void* const* d_in, const int* in_sizes, int n_in,
                              void* d_out, int out_size) {
    const float* logits = (const float*)d_in[0];
    const unsigned int* labels = (const unsigned int*)d_in[1];
    const float* cm     = (const float*)d_in[2];
    float* out = (float*)d_out;

    row_lse_kernel<<<N_ROWS, 256>>>(logits, labels, cm);

    cudaLaunchConfig_t cfg = {};
    cfg.gridDim  = dim3(1, 1, 1);
    cfg.blockDim = dim3(1, 1, 1);
    cfg.dynamicSmemBytes = 0;
    cudaLaunchAttribute attrs[1];
    attrs[0].id = cudaLaunchAttributeProgrammaticStreamSerialization;
    attrs[0].val.programmaticStreamSerializationAllowed = 1;
    cfg.attrs = attrs;
    cfg.numAttrs = 1;
    cudaLaunchKernelEx(&cfg, finalize_kernel, out);
}